// round 4
// baseline (speedup 1.0000x reference)
#include <cuda_runtime.h>

// TwoCompartmentLIF: T=50 steps, N=500000 neurons.
// Inputs (metadata order): g_exc_basal, g_inh_basal, g_nmda_basal, g_gaba_b_in,
//                          g_exc_apical, g_inh_apical, g_nmda_apical   each [T,N] f32
// Output: concat(spikes [T,N], v_trace [T,N]) f32
//
// Pure streaming problem: 700MB read + 200MB write, state in registers.
// 4 neurons per thread via float4; __ldcs/__stcs streaming (data touched once).

#define T_STEPS 50
#define N_NEUR  500000
#define N_VEC   (N_NEUR / 4)   // 125000 float4 lanes

// --- model constants (exact f32 of the python doubles) ---
#define G_L      0.05f
#define E_L      0.0f
#define G_L_D    0.03f
#define INV_C_D  2.0f          // DT / C_D
#define G_C      0.05f
#define E_E      3.0f
#define E_I      (-0.5f)
#define E_NMDA   3.0f
#define E_GABA_B (-0.8f)
#define E_CA     4.0f
#define V_TH     1.0f
#define V_RESET  0.0f
#define TAU_REF  5.0f
#define DT       1.0f
#define MG_K     5.0f
#define MG_VHALF 0.5f
#define THETA_CA 2.0f
#define G_CA_SPIKE 0.3f
#define BAP_AMP  0.3f
// decay factors exp(-dt/tau), double -> f32 rounding
#define D_E   0.81873075307798185867f   // exp(-1/5)
#define D_I   0.90483741803595957316f   // exp(-1/10)
#define D_N   0.99004983374916805357f   // exp(-1/100)
#define D_GB  0.99750312239746142239f   // exp(-1/400)
#define D_CA  0.95122942450071400910f   // exp(-1/20)
// gAd: initial 0 and ADAPT_INC == 0  =>  identically zero. Dropped.

__device__ __forceinline__ float sigmoidf_(float x) {
    return 1.0f / (1.0f + expf(-x));
}

__global__ __launch_bounds__(256)
void lif_kernel(const float4* __restrict__ inEb, const float4* __restrict__ inIb,
                const float4* __restrict__ inNb, const float4* __restrict__ inGB,
                const float4* __restrict__ inEa, const float4* __restrict__ inIa,
                const float4* __restrict__ inNa,
                float4* __restrict__ out_spk, float4* __restrict__ out_v)
{
    const int i = blockIdx.x * blockDim.x + threadIdx.x;
    if (i >= N_VEC) return;

    // per-lane state (E_L == 0 so everything starts at 0)
    float vs[4]  = {0.f, 0.f, 0.f, 0.f};
    float vd[4]  = {0.f, 0.f, 0.f, 0.f};
    float gEb[4] = {0.f, 0.f, 0.f, 0.f};
    float gIb[4] = {0.f, 0.f, 0.f, 0.f};
    float gNb[4] = {0.f, 0.f, 0.f, 0.f};
    float gGB[4] = {0.f, 0.f, 0.f, 0.f};
    float gEa[4] = {0.f, 0.f, 0.f, 0.f};
    float gIa[4] = {0.f, 0.f, 0.f, 0.f};
    float gNa[4] = {0.f, 0.f, 0.f, 0.f};
    float gCa[4] = {0.f, 0.f, 0.f, 0.f};
    float ref[4] = {0.f, 0.f, 0.f, 0.f};

    for (int t = 0; t < T_STEPS; ++t) {
        const int off = t * N_VEC + i;
        // 7 independent streaming loads -> high MLP
        float4 vEb = __ldcs(inEb + off);
        float4 vIb = __ldcs(inIb + off);
        float4 vNb = __ldcs(inNb + off);
        float4 vGB = __ldcs(inGB + off);
        float4 vEa = __ldcs(inEa + off);
        float4 vIa = __ldcs(inIa + off);
        float4 vNa = __ldcs(inNa + off);

        const float* pEb = reinterpret_cast<const float*>(&vEb);
        const float* pIb = reinterpret_cast<const float*>(&vIb);
        const float* pNb = reinterpret_cast<const float*>(&vNb);
        const float* pGB = reinterpret_cast<const float*>(&vGB);
        const float* pEa = reinterpret_cast<const float*>(&vEa);
        const float* pIa = reinterpret_cast<const float*>(&vIa);
        const float* pNa = reinterpret_cast<const float*>(&vNa);

        float spk[4], vout[4];

        #pragma unroll
        for (int l = 0; l < 4; ++l) {
            // decay + inject
            gEb[l] = gEb[l] * D_E  + pEb[l];
            gIb[l] = gIb[l] * D_I  + pIb[l];
            gNb[l] = gNb[l] * D_N  + pNb[l];
            gGB[l] = gGB[l] * D_GB + pGB[l];
            gEa[l] = gEa[l] * D_E  + pEa[l];
            gIa[l] = gIa[l] * D_I  + pIa[l];
            gNa[l] = gNa[l] * D_N  + pNa[l];
            gCa[l] = gCa[l] * D_CA;

            const float v_s = vs[l];
            const float v_d = vd[l];

            const float mg_s = sigmoidf_(MG_K * (v_s - MG_VHALF));
            const float mg_d = sigmoidf_(MG_K * (v_d - MG_VHALF));

            float I_s = G_L * (E_L - v_s)
                      + gEb[l] * (E_E - v_s)
                      + gIb[l] * (E_I - v_s)
                      + gNb[l] * mg_s * (E_NMDA - v_s)
                      + gGB[l] * (E_GABA_B - v_s)
                      + G_C * (v_d - v_s);

            float I_d = G_L_D * (E_L - v_d)
                      + gEa[l] * (E_E - v_d)
                      + gIa[l] * (E_I - v_d)
                      + gNa[l] * mg_d * (E_NMDA - v_d)
                      + gCa[l] * (E_CA - v_d)
                      + G_C * (v_s - v_d);

            const bool refractory = ref[l] > 0.0f;
            float v_s_new = refractory ? V_RESET : (v_s + DT * I_s);
            float v_d_new = v_d + INV_C_D * I_d;

            const bool spike = (v_s_new >= V_TH) && !refractory;
            const float spike_f = spike ? 1.0f : 0.0f;

            v_s_new = spike ? V_RESET : v_s_new;
            ref[l]  = spike ? TAU_REF : fmaxf(ref[l] - DT, 0.0f);
            // back-propagating AP
            v_d_new = spike ? (v_d_new + BAP_AMP * (E_CA - v_d_new)) : v_d_new;
            // dendritic Ca spike
            gCa[l] += (v_d_new >= THETA_CA) ? G_CA_SPIKE : 0.0f;

            vs[l] = v_s_new;
            vd[l] = v_d_new;
            spk[l]  = spike_f;
            vout[l] = v_s_new;
        }

        float4 s4; s4.x = spk[0]; s4.y = spk[1]; s4.z = spk[2]; s4.w = spk[3];
        float4 v4; v4.x = vout[0]; v4.y = vout[1]; v4.z = vout[2]; v4.w = vout[3];
        __stcs(out_spk + off, s4);
        __stcs(out_v   + off, v4);
    }
}

extern "C" void kernel_launch(void* const* d_in, const int* in_sizes, int n_in,
                              void* d_out, int out_size)
{
    const float4* inEb = (const float4*)d_in[0];
    const float4* inIb = (const float4*)d_in[1];
    const float4* inNb = (const float4*)d_in[2];
    const float4* inGB = (const float4*)d_in[3];
    const float4* inEa = (const float4*)d_in[4];
    const float4* inIa = (const float4*)d_in[5];
    const float4* inNa = (const float4*)d_in[6];

    float* out = (float*)d_out;
    float4* out_spk = (float4*)out;                                   // [T, N]
    float4* out_v   = (float4*)(out + (size_t)T_STEPS * N_NEUR);      // [T, N]

    const int threads = 256;
    const int blocks  = (N_VEC + threads - 1) / threads;  // 489
    lif_kernel<<<blocks, threads>>>(inEb, inIb, inNb, inGB, inEa, inIa, inNa,
                                    out_spk, out_v);
}

// round 6
// speedup vs baseline: 1.1702x; 1.1702x over previous
#include <cuda_runtime.h>

// TwoCompartmentLIF: T=50 steps, N=500000 neurons.
// R4 profile: 196.7us, DRAM 56.8%, occ 21.3% (86 regs, 489 CTAs) -> latency-bound.
// Fix: 2 neurons/thread (float2), halving register state -> ~2.5x more warps/SM,
// deeper SM-wide outstanding-load pool to saturate HBM.

#define T_STEPS 50
#define N_NEUR  500000
#define N_VEC   (N_NEUR / 2)   // 250000 float2 lanes

// --- model constants ---
#define G_L      0.05f
#define E_L      0.0f
#define G_L_D    0.03f
#define INV_C_D  2.0f          // DT / C_D
#define G_C      0.05f
#define E_E      3.0f
#define E_I      (-0.5f)
#define E_NMDA   3.0f
#define E_GABA_B (-0.8f)
#define E_CA     4.0f
#define V_TH     1.0f
#define V_RESET  0.0f
#define TAU_REF  5.0f
#define DT       1.0f
#define MG_K     5.0f
#define MG_VHALF 0.5f
#define THETA_CA 2.0f
#define G_CA_SPIKE 0.3f
#define BAP_AMP  0.3f
// decay factors exp(-dt/tau)
#define D_E   0.81873075307798185867f   // exp(-1/5)
#define D_I   0.90483741803595957316f   // exp(-1/10)
#define D_N   0.99004983374916805357f   // exp(-1/100)
#define D_GB  0.99750312239746142239f   // exp(-1/400)
#define D_CA  0.95122942450071400910f   // exp(-1/20)
// gAd identically zero (ADAPT_INC == 0) -> elided.

__device__ __forceinline__ float sigmoidf_(float x) {
    return 1.0f / (1.0f + expf(-x));
}

__global__ __launch_bounds__(256)
void lif_kernel(const float2* __restrict__ inEb, const float2* __restrict__ inIb,
                const float2* __restrict__ inNb, const float2* __restrict__ inGB,
                const float2* __restrict__ inEa, const float2* __restrict__ inIa,
                const float2* __restrict__ inNa,
                float2* __restrict__ out_spk, float2* __restrict__ out_v)
{
    const int i = blockIdx.x * blockDim.x + threadIdx.x;
    if (i >= N_VEC) return;

    float vs[2]  = {0.f, 0.f};
    float vd[2]  = {0.f, 0.f};
    float gEb[2] = {0.f, 0.f};
    float gIb[2] = {0.f, 0.f};
    float gNb[2] = {0.f, 0.f};
    float gGB[2] = {0.f, 0.f};
    float gEa[2] = {0.f, 0.f};
    float gIa[2] = {0.f, 0.f};
    float gNa[2] = {0.f, 0.f};
    float gCa[2] = {0.f, 0.f};
    float ref[2] = {0.f, 0.f};

    for (int t = 0; t < T_STEPS; ++t) {
        const int off = t * N_VEC + i;
        // 7 independent streaming loads
        float2 vEb = __ldcs(inEb + off);
        float2 vIb = __ldcs(inIb + off);
        float2 vNb = __ldcs(inNb + off);
        float2 vGB = __ldcs(inGB + off);
        float2 vEa = __ldcs(inEa + off);
        float2 vIa = __ldcs(inIa + off);
        float2 vNa = __ldcs(inNa + off);

        const float* pEb = reinterpret_cast<const float*>(&vEb);
        const float* pIb = reinterpret_cast<const float*>(&vIb);
        const float* pNb = reinterpret_cast<const float*>(&vNb);
        const float* pGB = reinterpret_cast<const float*>(&vGB);
        const float* pEa = reinterpret_cast<const float*>(&vEa);
        const float* pIa = reinterpret_cast<const float*>(&vIa);
        const float* pNa = reinterpret_cast<const float*>(&vNa);

        float spk[2], vout[2];

        #pragma unroll
        for (int l = 0; l < 2; ++l) {
            gEb[l] = gEb[l] * D_E  + pEb[l];
            gIb[l] = gIb[l] * D_I  + pIb[l];
            gNb[l] = gNb[l] * D_N  + pNb[l];
            gGB[l] = gGB[l] * D_GB + pGB[l];
            gEa[l] = gEa[l] * D_E  + pEa[l];
            gIa[l] = gIa[l] * D_I  + pIa[l];
            gNa[l] = gNa[l] * D_N  + pNa[l];
            gCa[l] = gCa[l] * D_CA;

            const float v_s = vs[l];
            const float v_d = vd[l];

            const float mg_s = sigmoidf_(MG_K * (v_s - MG_VHALF));
            const float mg_d = sigmoidf_(MG_K * (v_d - MG_VHALF));

            float I_s = G_L * (E_L - v_s)
                      + gEb[l] * (E_E - v_s)
                      + gIb[l] * (E_I - v_s)
                      + gNb[l] * mg_s * (E_NMDA - v_s)
                      + gGB[l] * (E_GABA_B - v_s)
                      + G_C * (v_d - v_s);

            float I_d = G_L_D * (E_L - v_d)
                      + gEa[l] * (E_E - v_d)
                      + gIa[l] * (E_I - v_d)
                      + gNa[l] * mg_d * (E_NMDA - v_d)
                      + gCa[l] * (E_CA - v_d)
                      + G_C * (v_s - v_d);

            const bool refractory = ref[l] > 0.0f;
            float v_s_new = refractory ? V_RESET : (v_s + DT * I_s);
            float v_d_new = v_d + INV_C_D * I_d;

            const bool spike = (v_s_new >= V_TH) && !refractory;
            const float spike_f = spike ? 1.0f : 0.0f;

            v_s_new = spike ? V_RESET : v_s_new;
            ref[l]  = spike ? TAU_REF : fmaxf(ref[l] - DT, 0.0f);
            v_d_new = spike ? (v_d_new + BAP_AMP * (E_CA - v_d_new)) : v_d_new;
            gCa[l] += (v_d_new >= THETA_CA) ? G_CA_SPIKE : 0.0f;

            vs[l] = v_s_new;
            vd[l] = v_d_new;
            spk[l]  = spike_f;
            vout[l] = v_s_new;
        }

        float2 s2; s2.x = spk[0]; s2.y = spk[1];
        float2 v2; v2.x = vout[0]; v2.y = vout[1];
        __stcs(out_spk + off, s2);
        __stcs(out_v   + off, v2);
    }
}

extern "C" void kernel_launch(void* const* d_in, const int* in_sizes, int n_in,
                              void* d_out, int out_size)
{
    const float2* inEb = (const float2*)d_in[0];
    const float2* inIb = (const float2*)d_in[1];
    const float2* inNb = (const float2*)d_in[2];
    const float2* inGB = (const float2*)d_in[3];
    const float2* inEa = (const float2*)d_in[4];
    const float2* inIa = (const float2*)d_in[5];
    const float2* inNa = (const float2*)d_in[6];

    float* out = (float*)d_out;
    float2* out_spk = (float2*)out;                                   // [T, N]
    float2* out_v   = (float2*)(out + (size_t)T_STEPS * N_NEUR);      // [T, N]

    const int threads = 256;
    const int blocks  = (N_VEC + threads - 1) / threads;  // 977
    lif_kernel<<<blocks, threads>>>(inEb, inIb, inNb, inGB, inEa, inIa, inNa,
                                    out_spk, out_v);
}

// round 10
// speedup vs baseline: 1.2966x; 1.1080x over previous
#include <cuda_runtime.h>

// TwoCompartmentLIF: T=50 steps, N=500000 neurons.
// R4: 196.7us float4/thread, 86 regs, occ 21%, DRAM 57%  (latency-bound)
// R6: 168.1us float2/thread, 48 regs, occ 48%, DRAM 66.5% (still latency-exposed)
// R7: 1 neuron/thread scalar -> ~36-40 regs -> 6-7 blocks/SM (~75-87% occ),
//     1954 CTAs. Goal: enough warps in flight to saturate HBM.

#define T_STEPS 50
#define N_NEUR  500000

// --- model constants ---
#define G_L      0.05f
#define E_L      0.0f
#define G_L_D    0.03f
#define INV_C_D  2.0f          // DT / C_D
#define G_C      0.05f
#define E_E      3.0f
#define E_I      (-0.5f)
#define E_NMDA   3.0f
#define E_GABA_B (-0.8f)
#define E_CA     4.0f
#define V_TH     1.0f
#define V_RESET  0.0f
#define TAU_REF  5.0f
#define DT       1.0f
#define MG_K     5.0f
#define MG_VHALF 0.5f
#define THETA_CA 2.0f
#define G_CA_SPIKE 0.3f
#define BAP_AMP  0.3f
// decay factors exp(-dt/tau)
#define D_E   0.81873075307798185867f   // exp(-1/5)
#define D_I   0.90483741803595957316f   // exp(-1/10)
#define D_N   0.99004983374916805357f   // exp(-1/100)
#define D_GB  0.99750312239746142239f   // exp(-1/400)
#define D_CA  0.95122942450071400910f   // exp(-1/20)
// gAd identically zero (ADAPT_INC == 0) -> elided.

__device__ __forceinline__ float sigmoidf_(float x) {
    return 1.0f / (1.0f + expf(-x));
}

__global__ __launch_bounds__(256)
void lif_kernel(const float* __restrict__ inEb, const float* __restrict__ inIb,
                const float* __restrict__ inNb, const float* __restrict__ inGB,
                const float* __restrict__ inEa, const float* __restrict__ inIa,
                const float* __restrict__ inNa,
                float* __restrict__ out_spk, float* __restrict__ out_v)
{
    const int i = blockIdx.x * blockDim.x + threadIdx.x;
    if (i >= N_NEUR) return;

    float vs  = 0.f, vd  = 0.f;
    float gEb = 0.f, gIb = 0.f, gNb = 0.f, gGB = 0.f;
    float gEa = 0.f, gIa = 0.f, gNa = 0.f, gCa = 0.f;
    float ref = 0.f;

    for (int t = 0; t < T_STEPS; ++t) {
        const int off = t * N_NEUR + i;
        // 7 independent streaming loads (front-batched -> MLP 7)
        const float xEb = __ldcs(inEb + off);
        const float xIb = __ldcs(inIb + off);
        const float xNb = __ldcs(inNb + off);
        const float xGB = __ldcs(inGB + off);
        const float xEa = __ldcs(inEa + off);
        const float xIa = __ldcs(inIa + off);
        const float xNa = __ldcs(inNa + off);

        gEb = gEb * D_E  + xEb;
        gIb = gIb * D_I  + xIb;
        gNb = gNb * D_N  + xNb;
        gGB = gGB * D_GB + xGB;
        gEa = gEa * D_E  + xEa;
        gIa = gIa * D_I  + xIa;
        gNa = gNa * D_N  + xNa;
        gCa = gCa * D_CA;

        const float mg_s = sigmoidf_(MG_K * (vs - MG_VHALF));
        const float mg_d = sigmoidf_(MG_K * (vd - MG_VHALF));

        float I_s = G_L * (E_L - vs)
                  + gEb * (E_E - vs)
                  + gIb * (E_I - vs)
                  + gNb * mg_s * (E_NMDA - vs)
                  + gGB * (E_GABA_B - vs)
                  + G_C * (vd - vs);

        float I_d = G_L_D * (E_L - vd)
                  + gEa * (E_E - vd)
                  + gIa * (E_I - vd)
                  + gNa * mg_d * (E_NMDA - vd)
                  + gCa * (E_CA - vd)
                  + G_C * (vs - vd);

        const bool refractory = ref > 0.0f;
        float v_s_new = refractory ? V_RESET : (vs + DT * I_s);
        float v_d_new = vd + INV_C_D * I_d;

        const bool spike = (v_s_new >= V_TH) && !refractory;
        const float spike_f = spike ? 1.0f : 0.0f;

        v_s_new = spike ? V_RESET : v_s_new;
        ref     = spike ? TAU_REF : fmaxf(ref - DT, 0.0f);
        v_d_new = spike ? (v_d_new + BAP_AMP * (E_CA - v_d_new)) : v_d_new;
        gCa    += (v_d_new >= THETA_CA) ? G_CA_SPIKE : 0.0f;

        vs = v_s_new;
        vd = v_d_new;

        __stcs(out_spk + off, spike_f);
        __stcs(out_v   + off, v_s_new);
    }
}

extern "C" void kernel_launch(void* const* d_in, const int* in_sizes, int n_in,
                              void* d_out, int out_size)
{
    const float* inEb = (const float*)d_in[0];
    const float* inIb = (const float*)d_in[1];
    const float* inNb = (const float*)d_in[2];
    const float* inGB = (const float*)d_in[3];
    const float* inEa = (const float*)d_in[4];
    const float* inIa = (const float*)d_in[5];
    const float* inNa = (const float*)d_in[6];

    float* out = (float*)d_out;
    float* out_spk = out;                                   // [T, N]
    float* out_v   = out + (size_t)T_STEPS * N_NEUR;        // [T, N]

    const int threads = 256;
    const int blocks  = (N_NEUR + threads - 1) / threads;   // 1954
    lif_kernel<<<blocks, threads>>>(inEb, inIb, inNb, inGB, inEa, inIa, inNa,
                                    out_spk, out_v);
}